// round 1
// baseline (speedup 1.0000x reference)
#include <cuda_runtime.h>
#include <math.h>

#define NB 256      // batch
#define NS 196      // seq
#define ND 1024     // dim
#define NP 512      // pool
#define NL 8        // length
#define TOPK 4
#define SSPLIT 4
#define SCHUNK 49   // 196/4

// ---------------- scratch (no allocations allowed) ----------------
__device__ float g_part[SSPLIT * NB * ND];   // 4 MB partial sums
__device__ float g_qn[NB * ND];              // normalized query
__device__ float g_kn[NP * ND];              // normalized keys
__device__ float g_sim[NB * NP];             // similarity matrix

// ---------------- K1: partial mean over seq ----------------
// grid (NB, SSPLIT), 256 threads; each thread owns one float4 of D.
__global__ void k_mean_partial(const float* __restrict__ x) {
    int b = blockIdx.x, sp = blockIdx.y, tid = threadIdx.x;
    const float4* xp = (const float4*)x + (size_t)(b * NS + sp * SCHUNK) * (ND / 4) + tid;
    float4 acc = make_float4(0.f, 0.f, 0.f, 0.f);
#pragma unroll 7
    for (int s = 0; s < SCHUNK; ++s) {
        float4 v = xp[(size_t)s * (ND / 4)];
        acc.x += v.x; acc.y += v.y; acc.z += v.z; acc.w += v.w;
    }
    ((float4*)g_part)[(sp * NB + b) * (ND / 4) + tid] = acc;
}

// ---------------- K2: combine partials + L2 normalize (query & keys) ----------
// grid NB+NP blocks, 256 threads. blocks [0,NB): query; [NB,NB+NP): keys.
__global__ void k_finalize(const float* __restrict__ key) {
    __shared__ float red[256];
    int blk = blockIdx.x, tid = threadIdx.x;
    float4 q;
    float* op;
    if (blk < NB) {
        const float4* pp = (const float4*)g_part;
        float4 p0 = pp[(0 * NB + blk) * (ND / 4) + tid];
        float4 p1 = pp[(1 * NB + blk) * (ND / 4) + tid];
        float4 p2 = pp[(2 * NB + blk) * (ND / 4) + tid];
        float4 p3 = pp[(3 * NB + blk) * (ND / 4) + tid];
        q.x = ((p0.x + p1.x) + (p2.x + p3.x)) / (float)NS;
        q.y = ((p0.y + p1.y) + (p2.y + p3.y)) / (float)NS;
        q.z = ((p0.z + p1.z) + (p2.z + p3.z)) / (float)NS;
        q.w = ((p0.w + p1.w) + (p2.w + p3.w)) / (float)NS;
        op = g_qn + (size_t)blk * ND;
    } else {
        int p = blk - NB;
        q = ((const float4*)key)[p * (ND / 4) + tid];
        op = g_kn + (size_t)p * ND;
    }
    float ss = q.x * q.x + q.y * q.y + q.z * q.z + q.w * q.w;
    red[tid] = ss;
    __syncthreads();
    for (int s = 128; s > 0; s >>= 1) {
        if (tid < s) red[tid] += red[tid + s];
        __syncthreads();
    }
    float rs = rsqrtf(fmaxf(red[0], 1e-12f));
    ((float4*)op)[tid] = make_float4(q.x * rs, q.y * rs, q.z * rs, q.w * rs);
}

// ---------------- K3: sim = q_n @ key_n^T  (fp32, NT dot-product form) -------
// Tile 32x32, 256 threads, 2x2 outputs/thread (rows {tr,tr+16}, cols {tc,tc+16}),
// float4 accumulation along k. Grid (NP/32=16, NB/32=8) = 128 blocks, 1 wave.
#define KC 32
#define SPAD 36
__global__ void k_gemm() {
    __shared__ float As[32 * SPAD];
    __shared__ float Bs[32 * SPAD];
    int tid = threadIdx.x;
    int m0 = blockIdx.y * 32, n0 = blockIdx.x * 32;
    int tr = tid >> 4;          // 0..15
    int tc = tid & 15;          // 0..15
    int lm = tid >> 3;          // 0..31 (loader row)
    int lc4 = tid & 7;          // 0..7  (loader float4 col)

    const float4* Ag = (const float4*)g_qn;
    const float4* Bg = (const float4*)g_kn;

    float4 a00 = make_float4(0.f, 0.f, 0.f, 0.f), a01 = a00, a10 = a00, a11 = a00;

    for (int kt = 0; kt < ND; kt += KC) {
        float4 av = Ag[(m0 + lm) * (ND / 4) + (kt >> 2) + lc4];
        float4 bv = Bg[(n0 + lm) * (ND / 4) + (kt >> 2) + lc4];
        __syncthreads();
        *(float4*)&As[lm * SPAD + lc4 * 4] = av;
        *(float4*)&Bs[lm * SPAD + lc4 * 4] = bv;
        __syncthreads();
#pragma unroll
        for (int k = 0; k < KC; k += 4) {
            float4 ra0 = *(const float4*)&As[tr * SPAD + k];
            float4 ra1 = *(const float4*)&As[(tr + 16) * SPAD + k];
            float4 rb0 = *(const float4*)&Bs[tc * SPAD + k];
            float4 rb1 = *(const float4*)&Bs[(tc + 16) * SPAD + k];
            a00.x += ra0.x * rb0.x; a00.y += ra0.y * rb0.y; a00.z += ra0.z * rb0.z; a00.w += ra0.w * rb0.w;
            a01.x += ra0.x * rb1.x; a01.y += ra0.y * rb1.y; a01.z += ra0.z * rb1.z; a01.w += ra0.w * rb1.w;
            a10.x += ra1.x * rb0.x; a10.y += ra1.y * rb0.y; a10.z += ra1.z * rb0.z; a10.w += ra1.w * rb0.w;
            a11.x += ra1.x * rb1.x; a11.y += ra1.y * rb1.y; a11.z += ra1.z * rb1.z; a11.w += ra1.w * rb1.w;
        }
    }
    g_sim[(m0 + tr) * NP + n0 + tc]           = (a00.x + a00.y) + (a00.z + a00.w);
    g_sim[(m0 + tr) * NP + n0 + tc + 16]      = (a01.x + a01.y) + (a01.z + a01.w);
    g_sim[(m0 + tr + 16) * NP + n0 + tc]      = (a10.x + a10.y) + (a10.z + a10.w);
    g_sim[(m0 + tr + 16) * NP + n0 + tc + 16] = (a11.x + a11.y) + (a11.z + a11.w);
}

// ---------------- K4: gumbel top-k selection + gather --------------------
__device__ __forceinline__ float gumbelf(float u) {
    float t = -logf(u + 1e-10f);
    return -logf(t + 1e-10f);
}

__global__ void k_select(const float* __restrict__ gum,
                         const float* __restrict__ prompt,
                         float* __restrict__ out) {
    __shared__ float cur[NP];
    __shared__ float rval[256];
    __shared__ int   ridx[256];
    __shared__ int   best[TOPK];
    int b = blockIdx.x, tid = threadIdx.x;

    cur[tid]       = g_sim[b * NP + tid];
    cur[tid + 256] = g_sim[b * NP + tid + 256];
    __syncthreads();

    for (int i = 0; i < TOPK; ++i) {
        const float* u = gum + ((size_t)i * NB + b) * NP;
        float v0 = cur[tid]       + gumbelf(u[tid]);
        float v1 = cur[tid + 256] + gumbelf(u[tid + 256]);
        float v; int idx;
        if (v1 > v0) { v = v1; idx = tid + 256; } else { v = v0; idx = tid; }
        rval[tid] = v; ridx[tid] = idx;
        __syncthreads();
        for (int s = 128; s > 0; s >>= 1) {
            if (tid < s) {
                float vb = rval[tid + s];
                // ties -> lowest index (matches jnp.argmax)
                if (vb > rval[tid] || (vb == rval[tid] && ridx[tid + s] < ridx[tid])) {
                    rval[tid] = vb; ridx[tid] = ridx[tid + s];
                }
            }
            __syncthreads();
        }
        if (tid == 0) { best[i] = ridx[0]; cur[ridx[0]] -= 1000.0f; }
        __syncthreads();
    }

    // gather: out[b, i*L + l, :] = prompt[best[i], l, :]
    float4* ob = (float4*)out + (size_t)b * TOPK * NL * (ND / 4);
#pragma unroll
    for (int i = 0; i < TOPK; ++i) {
        const float4* src = (const float4*)prompt + (size_t)best[i] * NL * (ND / 4);
        float4* dst = ob + i * NL * (ND / 4);
#pragma unroll
        for (int j = tid; j < NL * (ND / 4); j += 256)
            dst[j] = src[j];
    }
}

// ---------------- launch ----------------
extern "C" void kernel_launch(void* const* d_in, const int* in_sizes, int n_in,
                              void* d_out, int out_size) {
    const float* x      = (const float*)d_in[0];  // [256,196,1024]
    const float* prompt = (const float*)d_in[1];  // [512,8,1024]
    const float* key    = (const float*)d_in[2];  // [512,1024]
    const float* gum    = (const float*)d_in[3];  // [4,256,512]
    float* out          = (float*)d_out;          // [256,32,1024]

    k_mean_partial<<<dim3(NB, SSPLIT), 256>>>(x);
    k_finalize<<<NB + NP, 256>>>(key);
    k_gemm<<<dim3(NP / 32, NB / 32), 256>>>();
    k_select<<<NB, 256>>>(gum, prompt, out);
}

// round 2
// speedup vs baseline: 1.2331x; 1.2331x over previous
#include <cuda_runtime.h>
#include <math.h>

#define NB 256      // batch
#define NS 196      // seq
#define ND 1024     // dim
#define NP 512      // pool
#define NL 8        // length
#define TOPK 4
#define SSPLIT 7
#define SCHUNK 28   // 196/7

// GEMM config
#define TM 64
#define TN 64
#define GKC 32
#define SPLITK 8
#define KSLICE (ND / SPLITK)   // 128
#define APAD 68                // row stride (floats), 16B-aligned

// ---------------- scratch (no allocations allowed) ----------------
__device__ float g_part[SSPLIT * NB * ND];       // partial sums (7 MB)
__device__ float g_qn[NB * ND];                  // normalized query
__device__ float g_kn[NP * ND];                  // normalized keys
__device__ float g_simp[SPLITK * NB * NP];       // split-K GEMM partials (4 MB)
__device__ int   g_best[NB * TOPK];              // selected indices

// ---------------- K1: partial mean over seq ----------------
// grid (NB, SSPLIT), 256 threads; each thread owns one float4 of D.
__global__ void k_mean_partial(const float* __restrict__ x) {
    int b = blockIdx.x, sp = blockIdx.y, tid = threadIdx.x;
    const float4* xp = (const float4*)x + (size_t)(b * NS + sp * SCHUNK) * (ND / 4) + tid;
    float4 a0 = make_float4(0.f, 0.f, 0.f, 0.f);
    float4 a1 = make_float4(0.f, 0.f, 0.f, 0.f);
#pragma unroll 14
    for (int s = 0; s < SCHUNK; s += 2) {
        float4 v0 = xp[(size_t)s * (ND / 4)];
        float4 v1 = xp[(size_t)(s + 1) * (ND / 4)];
        a0.x += v0.x; a0.y += v0.y; a0.z += v0.z; a0.w += v0.w;
        a1.x += v1.x; a1.y += v1.y; a1.z += v1.z; a1.w += v1.w;
    }
    a0.x += a1.x; a0.y += a1.y; a0.z += a1.z; a0.w += a1.w;
    ((float4*)g_part)[(sp * NB + b) * (ND / 4) + tid] = a0;
}

// ---------------- K2: combine partials + L2 normalize (query & keys) ----------
__global__ void k_finalize(const float* __restrict__ key) {
    __shared__ float red[256];
    int blk = blockIdx.x, tid = threadIdx.x;
    float4 q;
    float* op;
    if (blk < NB) {
        const float4* pp = (const float4*)g_part;
        float4 acc = pp[(0 * NB + blk) * (ND / 4) + tid];
#pragma unroll
        for (int s = 1; s < SSPLIT; ++s) {
            float4 p = pp[(s * NB + blk) * (ND / 4) + tid];
            acc.x += p.x; acc.y += p.y; acc.z += p.z; acc.w += p.w;
        }
        q.x = acc.x / (float)NS; q.y = acc.y / (float)NS;
        q.z = acc.z / (float)NS; q.w = acc.w / (float)NS;
        op = g_qn + (size_t)blk * ND;
    } else {
        int p = blk - NB;
        q = ((const float4*)key)[p * (ND / 4) + tid];
        op = g_kn + (size_t)p * ND;
    }
    float ss = q.x * q.x + q.y * q.y + q.z * q.z + q.w * q.w;
    red[tid] = ss;
    __syncthreads();
    for (int s = 128; s > 0; s >>= 1) {
        if (tid < s) red[tid] += red[tid + s];
        __syncthreads();
    }
    float rs = rsqrtf(fmaxf(red[0], 1e-12f));
    ((float4*)op)[tid] = make_float4(q.x * rs, q.y * rs, q.z * rs, q.w * rs);
}

// ---------------- K3: sim partials = q_n @ key_n^T (fp32, split-K) ----------
// 64x64 tile, 256 threads, 4x4 per thread, KC=32, split-K=8.
__global__ void k_gemm() {
    __shared__ float As[GKC][APAD];   // [k][m]
    __shared__ float Bs[GKC][APAD];   // [k][n]
    int tid = threadIdx.x;
    int n0 = blockIdx.x * TN, m0 = blockIdx.y * TM, ks = blockIdx.z;
    int k0 = ks * KSLICE;
    int tr = tid >> 4, tc = tid & 15;

    int r0 = tid >> 3;   // 0..31 (loader row)
    int kq = tid & 7;    // 0..7  (loader float4 within 32-k chunk)

    const float4* Ag = (const float4*)g_qn;
    const float4* Bg = (const float4*)g_kn;

    float acc[4][4] = {};

    // prefetch first tile
    int kb = (k0 >> 2) + kq;
    float4 pa0 = Ag[(m0 + r0) * (ND / 4) + kb];
    float4 pa1 = Ag[(m0 + r0 + 32) * (ND / 4) + kb];
    float4 pb0 = Bg[(n0 + r0) * (ND / 4) + kb];
    float4 pb1 = Bg[(n0 + r0 + 32) * (ND / 4) + kb];

    for (int kt = 0; kt < KSLICE; kt += GKC) {
        __syncthreads();
        int kk = kq * 4;
        As[kk + 0][r0] = pa0.x; As[kk + 1][r0] = pa0.y;
        As[kk + 2][r0] = pa0.z; As[kk + 3][r0] = pa0.w;
        As[kk + 0][r0 + 32] = pa1.x; As[kk + 1][r0 + 32] = pa1.y;
        As[kk + 2][r0 + 32] = pa1.z; As[kk + 3][r0 + 32] = pa1.w;
        Bs[kk + 0][r0] = pb0.x; Bs[kk + 1][r0] = pb0.y;
        Bs[kk + 2][r0] = pb0.z; Bs[kk + 3][r0] = pb0.w;
        Bs[kk + 0][r0 + 32] = pb1.x; Bs[kk + 1][r0 + 32] = pb1.y;
        Bs[kk + 2][r0 + 32] = pb1.z; Bs[kk + 3][r0 + 32] = pb1.w;
        __syncthreads();
        if (kt + GKC < KSLICE) {
            int kb2 = ((k0 + kt + GKC) >> 2) + kq;
            pa0 = Ag[(m0 + r0) * (ND / 4) + kb2];
            pa1 = Ag[(m0 + r0 + 32) * (ND / 4) + kb2];
            pb0 = Bg[(n0 + r0) * (ND / 4) + kb2];
            pb1 = Bg[(n0 + r0 + 32) * (ND / 4) + kb2];
        }
#pragma unroll
        for (int k = 0; k < GKC; ++k) {
            float4 a4 = *(const float4*)&As[k][tr * 4];
            float4 b4 = *(const float4*)&Bs[k][tc * 4];
            acc[0][0] += a4.x * b4.x; acc[0][1] += a4.x * b4.y;
            acc[0][2] += a4.x * b4.z; acc[0][3] += a4.x * b4.w;
            acc[1][0] += a4.y * b4.x; acc[1][1] += a4.y * b4.y;
            acc[1][2] += a4.y * b4.z; acc[1][3] += a4.y * b4.w;
            acc[2][0] += a4.z * b4.x; acc[2][1] += a4.z * b4.y;
            acc[2][2] += a4.z * b4.z; acc[2][3] += a4.z * b4.w;
            acc[3][0] += a4.w * b4.x; acc[3][1] += a4.w * b4.y;
            acc[3][2] += a4.w * b4.z; acc[3][3] += a4.w * b4.w;
        }
    }
#pragma unroll
    for (int i = 0; i < 4; ++i) {
        float4 v = make_float4(acc[i][0], acc[i][1], acc[i][2], acc[i][3]);
        *(float4*)&g_simp[((size_t)ks * NB + m0 + tr * 4 + i) * NP + n0 + tc * 4] = v;
    }
}

// ---------------- K4a: gumbel top-k selection (indices only) -------------
__device__ __forceinline__ float gumbelf(float u) {
    float t = -logf(u + 1e-10f);
    return -logf(t + 1e-10f);
}

__global__ void k_select_idx(const float* __restrict__ gum) {
    __shared__ float wval[16];
    __shared__ int   widx[16];
    __shared__ int   sbest;
    int b = blockIdx.x, p = threadIdx.x;
    int lane = p & 31, w = p >> 5;

    // reduce split-K partials for this (b,p)
    float cur = 0.f;
#pragma unroll
    for (int s = 0; s < SPLITK; ++s)
        cur += g_simp[((size_t)s * NB + b) * NP + p];

    // precompute all 4 gumbel noises for this p
    float g[TOPK];
#pragma unroll
    for (int i = 0; i < TOPK; ++i)
        g[i] = gumbelf(gum[((size_t)i * NB + b) * NP + p]);

    for (int i = 0; i < TOPK; ++i) {
        float v = cur + g[i];
        int idx = p;
#pragma unroll
        for (int o = 16; o > 0; o >>= 1) {
            float ov = __shfl_down_sync(0xFFFFFFFFu, v, o);
            int   oi = __shfl_down_sync(0xFFFFFFFFu, idx, o);
            if (ov > v || (ov == v && oi < idx)) { v = ov; idx = oi; }
        }
        if (lane == 0) { wval[w] = v; widx[w] = idx; }
        __syncthreads();
        if (w == 0) {
            float v2 = wval[lane & 15];
            int   i2 = widx[lane & 15];
#pragma unroll
            for (int o = 8; o > 0; o >>= 1) {
                float ov = __shfl_down_sync(0xFFFFFFFFu, v2, o);
                int   oi = __shfl_down_sync(0xFFFFFFFFu, i2, o);
                if (ov > v2 || (ov == v2 && oi < i2)) { v2 = ov; i2 = oi; }
            }
            if (lane == 0) { sbest = i2; g_best[b * TOPK + i] = i2; }
        }
        __syncthreads();
        if (p == sbest) cur -= 1000.0f;
        __syncthreads();
    }
}

// ---------------- K4b: gather selected prompts -> out --------------------
// grid NB*TOPK = 1024, 256 threads; each block copies 8x1024 floats (32 KB).
__global__ void k_gather(const float* __restrict__ prompt,
                         float* __restrict__ out) {
    int bi = blockIdx.x;
    int idx = g_best[bi];
    const float4* src = (const float4*)prompt + (size_t)idx * NL * (ND / 4);
    float4* dst = (float4*)out + (size_t)bi * NL * (ND / 4);
    int tid = threadIdx.x;
#pragma unroll
    for (int j = 0; j < 8; ++j)
        dst[tid + 256 * j] = src[tid + 256 * j];
}

// ---------------- launch ----------------
extern "C" void kernel_launch(void* const* d_in, const int* in_sizes, int n_in,
                              void* d_out, int out_size) {
    const float* x      = (const float*)d_in[0];  // [256,196,1024]
    const float* prompt = (const float*)d_in[1];  // [512,8,1024]
    const float* key    = (const float*)d_in[2];  // [512,1024]
    const float* gum    = (const float*)d_in[3];  // [4,256,512]
    float* out          = (float*)d_out;          // [256,32,1024]

    k_mean_partial<<<dim3(NB, SSPLIT), 256>>>(x);
    k_finalize<<<NB + NP, 256>>>(key);
    k_gemm<<<dim3(NP / TN, NB / TM, SPLITK), 256>>>();
    k_select_idx<<<NB, NP>>>(gum);
    k_gather<<<NB * TOPK, 256>>>(prompt, out);
}

// round 3
// speedup vs baseline: 1.2393x; 1.0050x over previous
#include <cuda_runtime.h>
#include <math.h>

#define NB 256      // batch
#define NS 196      // seq
#define ND 1024     // dim
#define NP 512      // pool
#define NL 8        // length
#define TOPK 4
#define SSPLIT 7
#define SCHUNK 28   // 196/7

// GEMM config
#define TM 64
#define TN 64
#define GKC 32
#define SPLITK 8
#define KSLICE (ND / SPLITK)   // 128
#define APAD 68                // row stride (floats), 16B-aligned

// ---------------- scratch (no allocations allowed) ----------------
__device__ float g_part[SSPLIT * NB * ND];       // partial sums (7 MB)
__device__ float g_q[NB * ND];                   // mean query (un-normalized)
__device__ float g_qs[NB];                       // 1/||q|| per batch
__device__ float g_ks[NP];                       // 1/||k|| per pool row
__device__ float g_simp[SPLITK * NB * NP];       // split-K GEMM partials (4 MB)
__device__ int   g_best[NB * TOPK];              // selected indices

// ---------------- K1: partial mean over seq ----------------
__global__ void k_mean_partial(const float* __restrict__ x) {
    int b = blockIdx.x, sp = blockIdx.y, tid = threadIdx.x;
    const float4* xp = (const float4*)x + (size_t)(b * NS + sp * SCHUNK) * (ND / 4) + tid;
    float4 a0 = make_float4(0.f, 0.f, 0.f, 0.f);
    float4 a1 = make_float4(0.f, 0.f, 0.f, 0.f);
#pragma unroll 14
    for (int s = 0; s < SCHUNK; s += 2) {
        float4 v0 = xp[(size_t)s * (ND / 4)];
        float4 v1 = xp[(size_t)(s + 1) * (ND / 4)];
        a0.x += v0.x; a0.y += v0.y; a0.z += v0.z; a0.w += v0.w;
        a1.x += v1.x; a1.y += v1.y; a1.z += v1.z; a1.w += v1.w;
    }
    a0.x += a1.x; a0.y += a1.y; a0.z += a1.z; a0.w += a1.w;
    ((float4*)g_part)[(sp * NB + b) * (ND / 4) + tid] = a0;
}

// ---------------- K2: combine partials, compute inverse norms -------------
// blocks [0,NB): mean -> g_q + g_qs.  blocks [NB,NB+NP): key norms -> g_ks.
__global__ void k_norms(const float* __restrict__ key) {
    __shared__ float red[256];
    int blk = blockIdx.x, tid = threadIdx.x;
    float4 q;
    if (blk < NB) {
        const float4* pp = (const float4*)g_part;
        float4 acc = pp[(0 * NB + blk) * (ND / 4) + tid];
#pragma unroll
        for (int s = 1; s < SSPLIT; ++s) {
            float4 p = pp[(s * NB + blk) * (ND / 4) + tid];
            acc.x += p.x; acc.y += p.y; acc.z += p.z; acc.w += p.w;
        }
        q.x = acc.x / (float)NS; q.y = acc.y / (float)NS;
        q.z = acc.z / (float)NS; q.w = acc.w / (float)NS;
        ((float4*)g_q)[blk * (ND / 4) + tid] = q;
    } else {
        q = ((const float4*)key)[(blk - NB) * (ND / 4) + tid];
    }
    float ss = q.x * q.x + q.y * q.y + q.z * q.z + q.w * q.w;
    red[tid] = ss;
    __syncthreads();
    for (int s = 128; s > 0; s >>= 1) {
        if (tid < s) red[tid] += red[tid + s];
        __syncthreads();
    }
    if (tid == 0) {
        float rs = rsqrtf(fmaxf(red[0], 1e-12f));
        if (blk < NB) g_qs[blk] = rs;
        else          g_ks[blk - NB] = rs;
    }
}

// ---------------- K3: raw dot products, split-K ---------------------------
// 64x64 tile, 256 threads, 4x4 per thread, KC=32, split-K=8.
__global__ void k_gemm(const float* __restrict__ key) {
    __shared__ float As[GKC][APAD];   // [k][m]
    __shared__ float Bs[GKC][APAD];   // [k][n]
    int tid = threadIdx.x;
    int n0 = blockIdx.x * TN, m0 = blockIdx.y * TM, ks = blockIdx.z;
    int k0 = ks * KSLICE;
    int tr = tid >> 4, tc = tid & 15;

    int r0 = tid >> 3;   // 0..31 (loader row)
    int kq = tid & 7;    // 0..7  (loader float4 within 32-k chunk)

    const float4* Ag = (const float4*)g_q;
    const float4* Bg = (const float4*)key;

    float acc[4][4] = {};

    int kb = (k0 >> 2) + kq;
    float4 pa0 = Ag[(m0 + r0) * (ND / 4) + kb];
    float4 pa1 = Ag[(m0 + r0 + 32) * (ND / 4) + kb];
    float4 pb0 = Bg[(n0 + r0) * (ND / 4) + kb];
    float4 pb1 = Bg[(n0 + r0 + 32) * (ND / 4) + kb];

    for (int kt = 0; kt < KSLICE; kt += GKC) {
        __syncthreads();
        int kk = kq * 4;
        As[kk + 0][r0] = pa0.x; As[kk + 1][r0] = pa0.y;
        As[kk + 2][r0] = pa0.z; As[kk + 3][r0] = pa0.w;
        As[kk + 0][r0 + 32] = pa1.x; As[kk + 1][r0 + 32] = pa1.y;
        As[kk + 2][r0 + 32] = pa1.z; As[kk + 3][r0 + 32] = pa1.w;
        Bs[kk + 0][r0] = pb0.x; Bs[kk + 1][r0] = pb0.y;
        Bs[kk + 2][r0] = pb0.z; Bs[kk + 3][r0] = pb0.w;
        Bs[kk + 0][r0 + 32] = pb1.x; Bs[kk + 1][r0 + 32] = pb1.y;
        Bs[kk + 2][r0 + 32] = pb1.z; Bs[kk + 3][r0 + 32] = pb1.w;
        __syncthreads();
        if (kt + GKC < KSLICE) {
            int kb2 = ((k0 + kt + GKC) >> 2) + kq;
            pa0 = Ag[(m0 + r0) * (ND / 4) + kb2];
            pa1 = Ag[(m0 + r0 + 32) * (ND / 4) + kb2];
            pb0 = Bg[(n0 + r0) * (ND / 4) + kb2];
            pb1 = Bg[(n0 + r0 + 32) * (ND / 4) + kb2];
        }
#pragma unroll
        for (int k = 0; k < GKC; ++k) {
            float4 a4 = *(const float4*)&As[k][tr * 4];
            float4 b4 = *(const float4*)&Bs[k][tc * 4];
            acc[0][0] += a4.x * b4.x; acc[0][1] += a4.x * b4.y;
            acc[0][2] += a4.x * b4.z; acc[0][3] += a4.x * b4.w;
            acc[1][0] += a4.y * b4.x; acc[1][1] += a4.y * b4.y;
            acc[1][2] += a4.y * b4.z; acc[1][3] += a4.y * b4.w;
            acc[2][0] += a4.z * b4.x; acc[2][1] += a4.z * b4.y;
            acc[2][2] += a4.z * b4.z; acc[2][3] += a4.z * b4.w;
            acc[3][0] += a4.w * b4.x; acc[3][1] += a4.w * b4.y;
            acc[3][2] += a4.w * b4.z; acc[3][3] += a4.w * b4.w;
        }
    }
#pragma unroll
    for (int i = 0; i < 4; ++i) {
        float4 v = make_float4(acc[i][0], acc[i][1], acc[i][2], acc[i][3]);
        *(float4*)&g_simp[((size_t)ks * NB + m0 + tr * 4 + i) * NP + n0 + tc * 4] = v;
    }
}

// ---------------- K4: gumbel top-k selection (exclusion form) -------------
__device__ __forceinline__ float gumbelf(float u) {
    float t = -logf(u + 1e-10f);
    return -logf(t + 1e-10f);
}

__global__ void k_select_idx(const float* __restrict__ gum) {
    __shared__ float wval[16];
    __shared__ int   widx[16];
    __shared__ int   best[TOPK];
    int b = blockIdx.x, p = threadIdx.x;
    int lane = p & 31, w = p >> 5;

    // reduce split-K partials, apply deferred normalization
    float cur = 0.f;
#pragma unroll
    for (int s = 0; s < SPLITK; ++s)
        cur += g_simp[((size_t)s * NB + b) * NP + p];
    cur *= g_qs[b] * g_ks[p];

    float g[TOPK];
#pragma unroll
    for (int i = 0; i < TOPK; ++i)
        g[i] = gumbelf(gum[((size_t)i * NB + b) * NP + p]);

    // sim in [-1,1], gumbel in [-3.2, 23.1] => a selected entry at -1000 can
    // never win again, so mask-out == index exclusion.
    for (int i = 0; i < TOPK; ++i) {
        bool excl = false;
#pragma unroll
        for (int j = 0; j < TOPK; ++j)
            if (j < i && best[j] == p) excl = true;
        float v = excl ? -1e30f : cur + g[i];
        int idx = p;
#pragma unroll
        for (int o = 16; o > 0; o >>= 1) {
            float ov = __shfl_down_sync(0xFFFFFFFFu, v, o);
            int   oi = __shfl_down_sync(0xFFFFFFFFu, idx, o);
            if (ov > v || (ov == v && oi < idx)) { v = ov; idx = oi; }
        }
        if (lane == 0) { wval[w] = v; widx[w] = idx; }
        __syncthreads();
        if (w == 0) {
            float v2 = wval[lane & 15];
            int   i2 = widx[lane & 15];
#pragma unroll
            for (int o = 8; o > 0; o >>= 1) {
                float ov = __shfl_down_sync(0xFFFFFFFFu, v2, o);
                int   oi = __shfl_down_sync(0xFFFFFFFFu, i2, o);
                if (ov > v2 || (ov == v2 && oi < i2)) { v2 = ov; i2 = oi; }
            }
            if (lane == 0) { best[i] = i2; g_best[b * TOPK + i] = i2; }
        }
        __syncthreads();
    }
}

// ---------------- K5: gather selected prompts -> out ----------------------
__global__ void k_gather(const float* __restrict__ prompt,
                         float* __restrict__ out) {
    int bi = blockIdx.x;
    int idx = g_best[bi];
    const float4* src = (const float4*)prompt + (size_t)idx * NL * (ND / 4);
    float4* dst = (float4*)out + (size_t)bi * NL * (ND / 4);
    int tid = threadIdx.x;
#pragma unroll
    for (int j = 0; j < 8; ++j)
        dst[tid + 256 * j] = src[tid + 256 * j];
}

// ---------------- launch ----------------
extern "C" void kernel_launch(void* const* d_in, const int* in_sizes, int n_in,
                              void* d_out, int out_size) {
    const float* x      = (const float*)d_in[0];  // [256,196,1024]
    const float* prompt = (const float*)d_in[1];  // [512,8,1024]
    const float* key    = (const float*)d_in[2];  // [512,1024]
    const float* gum    = (const float*)d_in[3];  // [4,256,512]
    float* out          = (float*)d_out;          // [256,32,1024]

    k_mean_partial<<<dim3(NB, SSPLIT), 256>>>(x);
    k_norms<<<NB + NP, 256>>>(key);
    k_gemm<<<dim3(NP / TN, NB / TM, SPLITK), 256>>>(key);
    k_select_idx<<<NB, NP>>>(gum);
    k_gather<<<NB * TOPK, 256>>>(prompt, out);
}

// round 4
// speedup vs baseline: 1.2410x; 1.0014x over previous
#include <cuda_runtime.h>
#include <math.h>

#define NB 256      // batch
#define NS 196      // seq
#define ND 1024     // dim
#define NP 512      // pool
#define NL 8        // length
#define TOPK 4
#define SSPLIT 7
#define SCHUNK 28   // 196/7

// GEMM config
#define TM 64
#define TN 128
#define GKC 32
#define SPLITK 8
#define KSLICE (ND / SPLITK)   // 128
#define ARS (TM * 2 + 4)       // As2 row stride in floats (dup A): 132
#define BRS (TN + 4)           // Bs  row stride in floats: 132

// ---------------- scratch (no allocations allowed) ----------------
__device__ float g_part[SSPLIT * NB * ND];       // partial sums (7 MB)
__device__ float g_q[NB * ND];                   // mean query (un-normalized)
__device__ float g_qs[NB];                       // 1/||q|| per batch
__device__ float g_ks[NP];                       // 1/||k|| per pool row
__device__ float g_simp[SPLITK * NB * NP];       // split-K GEMM partials (4 MB)

// packed dual-fp32 FMA (sm_100+): bitwise-identical to two scalar FFMAs
__device__ __forceinline__ unsigned long long ffma2(unsigned long long a,
                                                    unsigned long long b,
                                                    unsigned long long c) {
    unsigned long long d;
    asm("fma.rn.f32x2 %0, %1, %2, %3;" : "=l"(d) : "l"(a), "l"(b), "l"(c));
    return d;
}

// ---------------- K1: partial mean over seq ----------------
__global__ void k_mean_partial(const float* __restrict__ x) {
    int b = blockIdx.x, sp = blockIdx.y, tid = threadIdx.x;
    const float4* xp = (const float4*)x + (size_t)(b * NS + sp * SCHUNK) * (ND / 4) + tid;
    float4 a0 = make_float4(0.f, 0.f, 0.f, 0.f);
    float4 a1 = make_float4(0.f, 0.f, 0.f, 0.f);
#pragma unroll 14
    for (int s = 0; s < SCHUNK; s += 2) {
        float4 v0 = xp[(size_t)s * (ND / 4)];
        float4 v1 = xp[(size_t)(s + 1) * (ND / 4)];
        a0.x += v0.x; a0.y += v0.y; a0.z += v0.z; a0.w += v0.w;
        a1.x += v1.x; a1.y += v1.y; a1.z += v1.z; a1.w += v1.w;
    }
    a0.x += a1.x; a0.y += a1.y; a0.z += a1.z; a0.w += a1.w;
    ((float4*)g_part)[(sp * NB + b) * (ND / 4) + tid] = a0;
}

// ---------------- K2: combine partials, compute inverse norms -------------
__global__ void k_norms(const float* __restrict__ key) {
    __shared__ float red[256];
    int blk = blockIdx.x, tid = threadIdx.x;
    float4 q;
    if (blk < NB) {
        const float4* pp = (const float4*)g_part;
        float4 acc = pp[(0 * NB + blk) * (ND / 4) + tid];
#pragma unroll
        for (int s = 1; s < SSPLIT; ++s) {
            float4 p = pp[(s * NB + blk) * (ND / 4) + tid];
            acc.x += p.x; acc.y += p.y; acc.z += p.z; acc.w += p.w;
        }
        q.x = acc.x / (float)NS; q.y = acc.y / (float)NS;
        q.z = acc.z / (float)NS; q.w = acc.w / (float)NS;
        ((float4*)g_q)[blk * (ND / 4) + tid] = q;
    } else {
        q = ((const float4*)key)[(blk - NB) * (ND / 4) + tid];
    }
    float ss = q.x * q.x + q.y * q.y + q.z * q.z + q.w * q.w;
    red[tid] = ss;
    __syncthreads();
    for (int s = 128; s > 0; s >>= 1) {
        if (tid < s) red[tid] += red[tid + s];
        __syncthreads();
    }
    if (tid == 0) {
        float rs = rsqrtf(fmaxf(red[0], 1e-12f));
        if (blk < NB) g_qs[blk] = rs;
        else          g_ks[blk - NB] = rs;
    }
}

// ---------------- K3: raw dot products, split-K, FFMA2 --------------------
// 64x128 tile, 256 threads, 4 rows x 8 cols (4 col-pairs) per thread.
// A stored duplicated ({a,a}) so both operands load as LDS.64 pairs.
__global__ void k_gemm(const float* __restrict__ key) {
    __shared__ float As2[GKC][ARS];   // [k][2*m] duplicated
    __shared__ float Bs[GKC][BRS];    // [k][n]
    int tid = threadIdx.x;
    int n0 = blockIdx.x * TN, m0 = blockIdx.y * TM, ks = blockIdx.z;
    int k0 = ks * KSLICE;
    int tr = tid >> 4;          // 0..15 -> rows tr*4..tr*4+3
    int tc = tid & 15;          // 0..15 -> cols tc*8..tc*8+7

    const float4* Ag = (const float4*)g_q;
    const float4* Bg = (const float4*)key;

    // loader indices
    int am = tid >> 3;          // A: handles rows am, am+32 (wait: 512 f4 / 256 = 2)
    int akq = tid & 7;
    int bn = tid >> 3;          // B: rows bn, bn+32, bn+64, bn+96
    int bkq = tid & 7;

    unsigned long long acc[4][4];
#pragma unroll
    for (int i = 0; i < 4; ++i)
#pragma unroll
        for (int j = 0; j < 4; ++j) acc[i][j] = 0ULL;

    int kb = (k0 >> 2) + akq;
    float4 pa0 = Ag[(m0 + am) * (ND / 4) + kb];
    float4 pa1 = Ag[(m0 + am + 32) * (ND / 4) + kb];
    float4 pb0 = Bg[(n0 + bn) * (ND / 4) + kb];
    float4 pb1 = Bg[(n0 + bn + 32) * (ND / 4) + kb];
    float4 pb2 = Bg[(n0 + bn + 64) * (ND / 4) + kb];
    float4 pb3 = Bg[(n0 + bn + 96) * (ND / 4) + kb];

    for (int kt = 0; kt < KSLICE; kt += GKC) {
        __syncthreads();
        int kk = akq * 4;
        // A duplicated stores: As2[k][2m] = As2[k][2m+1] = a
        *(float2*)&As2[kk + 0][2 * am] = make_float2(pa0.x, pa0.x);
        *(float2*)&As2[kk + 1][2 * am] = make_float2(pa0.y, pa0.y);
        *(float2*)&As2[kk + 2][2 * am] = make_float2(pa0.z, pa0.z);
        *(float2*)&As2[kk + 3][2 * am] = make_float2(pa0.w, pa0.w);
        *(float2*)&As2[kk + 0][2 * (am + 32)] = make_float2(pa1.x, pa1.x);
        *(float2*)&As2[kk + 1][2 * (am + 32)] = make_float2(pa1.y, pa1.y);
        *(float2*)&As2[kk + 2][2 * (am + 32)] = make_float2(pa1.z, pa1.z);
        *(float2*)&As2[kk + 3][2 * (am + 32)] = make_float2(pa1.w, pa1.w);
        Bs[kk + 0][bn] = pb0.x; Bs[kk + 1][bn] = pb0.y;
        Bs[kk + 2][bn] = pb0.z; Bs[kk + 3][bn] = pb0.w;
        Bs[kk + 0][bn + 32] = pb1.x; Bs[kk + 1][bn + 32] = pb1.y;
        Bs[kk + 2][bn + 32] = pb1.z; Bs[kk + 3][bn + 32] = pb1.w;
        Bs[kk + 0][bn + 64] = pb2.x; Bs[kk + 1][bn + 64] = pb2.y;
        Bs[kk + 2][bn + 64] = pb2.z; Bs[kk + 3][bn + 64] = pb2.w;
        Bs[kk + 0][bn + 96] = pb3.x; Bs[kk + 1][bn + 96] = pb3.y;
        Bs[kk + 2][bn + 96] = pb3.z; Bs[kk + 3][bn + 96] = pb3.w;
        __syncthreads();
        if (kt + GKC < KSLICE) {
            int kb2 = ((k0 + kt + GKC) >> 2) + akq;
            pa0 = Ag[(m0 + am) * (ND / 4) + kb2];
            pa1 = Ag[(m0 + am + 32) * (ND / 4) + kb2];
            pb0 = Bg[(n0 + bn) * (ND / 4) + kb2];
            pb1 = Bg[(n0 + bn + 32) * (ND / 4) + kb2];
            pb2 = Bg[(n0 + bn + 64) * (ND / 4) + kb2];
            pb3 = Bg[(n0 + bn + 96) * (ND / 4) + kb2];
        }
#pragma unroll
        for (int k = 0; k < GKC; ++k) {
            unsigned long long a0 = *(const unsigned long long*)&As2[k][(tr * 4 + 0) * 2];
            unsigned long long a1 = *(const unsigned long long*)&As2[k][(tr * 4 + 1) * 2];
            unsigned long long a2 = *(const unsigned long long*)&As2[k][(tr * 4 + 2) * 2];
            unsigned long long a3 = *(const unsigned long long*)&As2[k][(tr * 4 + 3) * 2];
            unsigned long long b0 = *(const unsigned long long*)&Bs[k][tc * 8 + 0];
            unsigned long long b1 = *(const unsigned long long*)&Bs[k][tc * 8 + 2];
            unsigned long long b2 = *(const unsigned long long*)&Bs[k][tc * 8 + 4];
            unsigned long long b3 = *(const unsigned long long*)&Bs[k][tc * 8 + 6];
            acc[0][0] = ffma2(a0, b0, acc[0][0]); acc[0][1] = ffma2(a0, b1, acc[0][1]);
            acc[0][2] = ffma2(a0, b2, acc[0][2]); acc[0][3] = ffma2(a0, b3, acc[0][3]);
            acc[1][0] = ffma2(a1, b0, acc[1][0]); acc[1][1] = ffma2(a1, b1, acc[1][1]);
            acc[1][2] = ffma2(a1, b2, acc[1][2]); acc[1][3] = ffma2(a1, b3, acc[1][3]);
            acc[2][0] = ffma2(a2, b0, acc[2][0]); acc[2][1] = ffma2(a2, b1, acc[2][1]);
            acc[2][2] = ffma2(a2, b2, acc[2][2]); acc[2][3] = ffma2(a2, b3, acc[2][3]);
            acc[3][0] = ffma2(a3, b0, acc[3][0]); acc[3][1] = ffma2(a3, b1, acc[3][1]);
            acc[3][2] = ffma2(a3, b2, acc[3][2]); acc[3][3] = ffma2(a3, b3, acc[3][3]);
        }
    }
#pragma unroll
    for (int i = 0; i < 4; ++i) {
        float2 v0 = *(float2*)&acc[i][0];
        float2 v1 = *(float2*)&acc[i][1];
        float2 v2 = *(float2*)&acc[i][2];
        float2 v3 = *(float2*)&acc[i][3];
        size_t rb = ((size_t)ks * NB + m0 + tr * 4 + i) * NP + n0 + tc * 8;
        *(float4*)&g_simp[rb]     = make_float4(v0.x, v0.y, v1.x, v1.y);
        *(float4*)&g_simp[rb + 4] = make_float4(v2.x, v2.y, v3.x, v3.y);
    }
}

// ---------------- K4: fused gumbel top-k selection + gather ---------------
__device__ __forceinline__ float gumbelf(float u) {
    float t = -logf(u + 1e-10f);
    return -logf(t + 1e-10f);
}

__global__ void k_select_gather(const float* __restrict__ gum,
                                const float* __restrict__ prompt,
                                float* __restrict__ out) {
    __shared__ float wval[16];
    __shared__ int   widx[16];
    __shared__ int   best[TOPK];
    int b = blockIdx.x, p = threadIdx.x;
    int lane = p & 31, w = p >> 5;

    // reduce split-K partials, apply deferred normalization
    float cur = 0.f;
#pragma unroll
    for (int s = 0; s < SPLITK; ++s)
        cur += g_simp[((size_t)s * NB + b) * NP + p];
    cur *= g_qs[b] * g_ks[p];

    float g[TOPK];
#pragma unroll
    for (int i = 0; i < TOPK; ++i)
        g[i] = gumbelf(gum[((size_t)i * NB + b) * NP + p]);

    // sim in [-1,1], gumbel in [-3.2, 23.1] => a selected entry at -1000 can
    // never win again, so mask-out == index exclusion.
    for (int i = 0; i < TOPK; ++i) {
        bool excl = false;
#pragma unroll
        for (int j = 0; j < TOPK; ++j)
            if (j < i && best[j] == p) excl = true;
        float v = excl ? -1e30f : cur + g[i];
        int idx = p;
#pragma unroll
        for (int o = 16; o > 0; o >>= 1) {
            float ov = __shfl_down_sync(0xFFFFFFFFu, v, o);
            int   oi = __shfl_down_sync(0xFFFFFFFFu, idx, o);
            if (ov > v || (ov == v && oi < idx)) { v = ov; idx = oi; }
        }
        if (lane == 0) { wval[w] = v; widx[w] = idx; }
        __syncthreads();
        if (w == 0) {
            float v2 = wval[lane & 15];
            int   i2 = widx[lane & 15];
#pragma unroll
            for (int o = 8; o > 0; o >>= 1) {
                float ov = __shfl_down_sync(0xFFFFFFFFu, v2, o);
                int   oi = __shfl_down_sync(0xFFFFFFFFu, i2, o);
                if (ov > v2 || (ov == v2 && oi < i2)) { v2 = ov; i2 = oi; }
            }
            if (lane == 0) best[i] = i2;
        }
        __syncthreads();
    }

    // gather: out[b, i*L + l, :] = prompt[best[i], l, :]  (512 threads)
    float4* ob = (float4*)out + (size_t)b * TOPK * NL * (ND / 4);
#pragma unroll
    for (int i = 0; i < TOPK; ++i) {
        const float4* src = (const float4*)prompt + (size_t)best[i] * NL * (ND / 4);
        float4* dst = ob + i * NL * (ND / 4);
#pragma unroll
        for (int j = 0; j < 4; ++j)
            dst[p + 512 * j] = src[p + 512 * j];
    }
}

// ---------------- launch ----------------
extern "C" void kernel_launch(void* const* d_in, const int* in_sizes, int n_in,
                              void* d_out, int out_size) {
    const float* x      = (const float*)d_in[0];  // [256,196,1024]
    const float* prompt = (const float*)d_in[1];  // [512,8,1024]
    const float* key    = (const float*)d_in[2];  // [512,1024]
    const float* gum    = (const float*)d_in[3];  // [4,256,512]
    float* out          = (float*)d_out;          // [256,32,1024]

    k_mean_partial<<<dim3(NB, SSPLIT), 256>>>(x);
    k_norms<<<NB + NP, 256>>>(key);
    k_gemm<<<dim3(NP / TN, NB / TM, SPLITK), 256>>>(key);
    k_select_gather<<<NB, NP>>>(gum, prompt, out);
}

// round 7
// speedup vs baseline: 1.4439x; 1.1635x over previous
#include <cuda_runtime.h>
#include <math.h>

#define NB 256      // batch
#define NS 196      // seq
#define ND 1024     // dim
#define NP 512      // pool
#define NL 8        // length
#define TOPK 4
#define SSPLIT 7
#define SCHUNK 28   // 196/7

// GEMM config
#define TM 64
#define TN 128
#define GKC 32
#define SPLITK 8
#define KSLICE (ND / SPLITK)   // 128
#define ARS 132                // As2 row stride (floats)
#define BRS 132                // Bs row stride (floats), plain layout

// ---------------- scratch (no allocations allowed) ----------------
__device__ float g_part[SSPLIT * NB * ND];       // partial sums (7 MB)
__device__ float g_q[NB * ND];                   // mean query (un-normalized)
__device__ float g_qs[NB];                       // 1/||q|| per batch
__device__ float g_ks[NP];                       // 1/||k|| per pool row
__device__ float g_simp[SPLITK * NB * NP];       // split-K raw-dot partials

// packed dual-fp32 FMA (sm_100+): bitwise-identical to two scalar FFMAs
__device__ __forceinline__ unsigned long long ffma2(unsigned long long a,
                                                    unsigned long long b,
                                                    unsigned long long c) {
    unsigned long long d;
    asm("fma.rn.f32x2 %0, %1, %2, %3;" : "=l"(d) : "l"(a), "l"(b), "l"(c));
    return d;
}

// ---------------- K1: partial mean over seq ----------------
__global__ void k_mean_partial(const float* __restrict__ x) {
    int b = blockIdx.x, sp = blockIdx.y, tid = threadIdx.x;
    const float4* xp = (const float4*)x + (size_t)(b * NS + sp * SCHUNK) * (ND / 4) + tid;
    float4 a0 = make_float4(0.f, 0.f, 0.f, 0.f);
    float4 a1 = make_float4(0.f, 0.f, 0.f, 0.f);
#pragma unroll 14
    for (int s = 0; s < SCHUNK; s += 2) {
        float4 v0 = __ldcs(&xp[(size_t)s * (ND / 4)]);
        float4 v1 = __ldcs(&xp[(size_t)(s + 1) * (ND / 4)]);
        a0.x += v0.x; a0.y += v0.y; a0.z += v0.z; a0.w += v0.w;
        a1.x += v1.x; a1.y += v1.y; a1.z += v1.z; a1.w += v1.w;
    }
    a0.x += a1.x; a0.y += a1.y; a0.z += a1.z; a0.w += a1.w;
    ((float4*)g_part)[(sp * NB + b) * (ND / 4) + tid] = a0;
}

// ---------------- K2: combine partials, compute inverse norms -------------
__global__ void k_norms(const float* __restrict__ key) {
    __shared__ float red[256];
    int blk = blockIdx.x, tid = threadIdx.x;
    float4 q;
    if (blk < NB) {
        const float4* pp = (const float4*)g_part;
        float4 acc = pp[(0 * NB + blk) * (ND / 4) + tid];
#pragma unroll
        for (int s = 1; s < SSPLIT; ++s) {
            float4 p = pp[(s * NB + blk) * (ND / 4) + tid];
            acc.x += p.x; acc.y += p.y; acc.z += p.z; acc.w += p.w;
        }
        q.x = acc.x / (float)NS; q.y = acc.y / (float)NS;
        q.z = acc.z / (float)NS; q.w = acc.w / (float)NS;
        ((float4*)g_q)[blk * (ND / 4) + tid] = q;
    } else {
        q = ((const float4*)key)[(blk - NB) * (ND / 4) + tid];
    }
    float ss = q.x * q.x + q.y * q.y + q.z * q.z + q.w * q.w;
    red[tid] = ss;
    __syncthreads();
    for (int s = 128; s > 0; s >>= 1) {
        if (tid < s) red[tid] += red[tid + s];
        __syncthreads();
    }
    if (tid == 0) {
        float rs = rsqrtf(fmaxf(red[0], 1e-12f));
        if (blk < NB) g_qs[blk] = rs;
        else          g_ks[blk - NB] = rs;
    }
}

// ---------------- K3: raw dots = g_q @ key^T (split-K, FFMA2) -------------
// 64x128 tile, 256 threads (8 warps as 4x2, lanes as 4x8), 4 rows x 8 cols
// per thread. Per-lane B columns: {wn*64+lc*4 .. +3} and {+32 .. +35}:
// LDS.64 reads hit 8 distinct bank pairs per instruction -> conflict-free,
// no skew needed. A duplicated ({a,a}) for f32x2; A reads broadcast.
__global__ void k_gemm(const float* __restrict__ key) {
    __shared__ __align__(16) float As2[GKC][ARS];   // [k][2*m] duplicated
    __shared__ __align__(16) float Bs[GKC][BRS];    // [k][n] plain
    int tid = threadIdx.x;
    int n0 = blockIdx.x * TN, m0 = blockIdx.y * TM, ks = blockIdx.z;
    int k0 = ks * KSLICE;

    int w = tid >> 5, lane = tid & 31;
    int wm = w & 3, wn = w >> 2;
    int lr = lane >> 3, lc = lane & 7;
    int aoff = 2 * (wm * 16 + lr * 4);     // float index in As2 row
    int c0 = wn * 64 + lc * 4;             // first 4-col group
    int c1 = c0 + 32;                      // second 4-col group

    // loader indices (identical to R4's known-good store pattern)
    int am = tid >> 3;          // 0..31
    int kq = tid & 7;           // float4 within 32-k chunk

    const float4* Ag = (const float4*)g_q;
    const float4* Bg = (const float4*)key;

    unsigned long long acc[4][4];
#pragma unroll
    for (int i = 0; i < 4; ++i)
#pragma unroll
        for (int j = 0; j < 4; ++j) acc[i][j] = 0ULL;

    int kb = (k0 >> 2) + kq;
    float4 pa0 = Ag[(m0 + am) * (ND / 4) + kb];
    float4 pa1 = Ag[(m0 + am + 32) * (ND / 4) + kb];
    float4 pb0 = Bg[(n0 + am) * (ND / 4) + kb];
    float4 pb1 = Bg[(n0 + am + 32) * (ND / 4) + kb];
    float4 pb2 = Bg[(n0 + am + 64) * (ND / 4) + kb];
    float4 pb3 = Bg[(n0 + am + 96) * (ND / 4) + kb];

    for (int kt = 0; kt < KSLICE; kt += GKC) {
        __syncthreads();
        int kk = kq * 4;
        *(float2*)&As2[kk + 0][2 * am] = make_float2(pa0.x, pa0.x);
        *(float2*)&As2[kk + 1][2 * am] = make_float2(pa0.y, pa0.y);
        *(float2*)&As2[kk + 2][2 * am] = make_float2(pa0.z, pa0.z);
        *(float2*)&As2[kk + 3][2 * am] = make_float2(pa0.w, pa0.w);
        *(float2*)&As2[kk + 0][2 * (am + 32)] = make_float2(pa1.x, pa1.x);
        *(float2*)&As2[kk + 1][2 * (am + 32)] = make_float2(pa1.y, pa1.y);
        *(float2*)&As2[kk + 2][2 * (am + 32)] = make_float2(pa1.z, pa1.z);
        *(float2*)&As2[kk + 3][2 * (am + 32)] = make_float2(pa1.w, pa1.w);
        Bs[kk + 0][am]      = pb0.x; Bs[kk + 1][am]      = pb0.y;
        Bs[kk + 2][am]      = pb0.z; Bs[kk + 3][am]      = pb0.w;
        Bs[kk + 0][am + 32] = pb1.x; Bs[kk + 1][am + 32] = pb1.y;
        Bs[kk + 2][am + 32] = pb1.z; Bs[kk + 3][am + 32] = pb1.w;
        Bs[kk + 0][am + 64] = pb2.x; Bs[kk + 1][am + 64] = pb2.y;
        Bs[kk + 2][am + 64] = pb2.z; Bs[kk + 3][am + 64] = pb2.w;
        Bs[kk + 0][am + 96] = pb3.x; Bs[kk + 1][am + 96] = pb3.y;
        Bs[kk + 2][am + 96] = pb3.z; Bs[kk + 3][am + 96] = pb3.w;
        __syncthreads();
        if (kt + GKC < KSLICE) {
            int kb2 = ((k0 + kt + GKC) >> 2) + kq;
            pa0 = Ag[(m0 + am) * (ND / 4) + kb2];
            pa1 = Ag[(m0 + am + 32) * (ND / 4) + kb2];
            pb0 = Bg[(n0 + am) * (ND / 4) + kb2];
            pb1 = Bg[(n0 + am + 32) * (ND / 4) + kb2];
            pb2 = Bg[(n0 + am + 64) * (ND / 4) + kb2];
            pb3 = Bg[(n0 + am + 96) * (ND / 4) + kb2];
        }
#pragma unroll
        for (int k = 0; k < GKC; ++k) {
            unsigned long long a0 = *(const unsigned long long*)&As2[k][aoff + 0];
            unsigned long long a1 = *(const unsigned long long*)&As2[k][aoff + 2];
            unsigned long long a2 = *(const unsigned long long*)&As2[k][aoff + 4];
            unsigned long long a3 = *(const unsigned long long*)&As2[k][aoff + 6];
            unsigned long long b0 = *(const unsigned long long*)&Bs[k][c0 + 0];
            unsigned long long b1 = *(const unsigned long long*)&Bs[k][c0 + 2];
            unsigned long long b2 = *(const unsigned long long*)&Bs[k][c1 + 0];
            unsigned long long b3 = *(const unsigned long long*)&Bs[k][c1 + 2];
            acc[0][0] = ffma2(a0, b0, acc[0][0]); acc[0][1] = ffma2(a0, b1, acc[0][1]);
            acc[0][2] = ffma2(a0, b2, acc[0][2]); acc[0][3] = ffma2(a0, b3, acc[0][3]);
            acc[1][0] = ffma2(a1, b0, acc[1][0]); acc[1][1] = ffma2(a1, b1, acc[1][1]);
            acc[1][2] = ffma2(a1, b2, acc[1][2]); acc[1][3] = ffma2(a1, b3, acc[1][3]);
            acc[2][0] = ffma2(a2, b0, acc[2][0]); acc[2][1] = ffma2(a2, b1, acc[2][1]);
            acc[2][2] = ffma2(a2, b2, acc[2][2]); acc[2][3] = ffma2(a2, b3, acc[2][3]);
            acc[3][0] = ffma2(a3, b0, acc[3][0]); acc[3][1] = ffma2(a3, b1, acc[3][1]);
            acc[3][2] = ffma2(a3, b2, acc[3][2]); acc[3][3] = ffma2(a3, b3, acc[3][3]);
        }
    }
    int mt = wm * 16 + lr * 4;
#pragma unroll
    for (int i = 0; i < 4; ++i) {
        float2 v0 = *(float2*)&acc[i][0];
        float2 v1 = *(float2*)&acc[i][1];
        float2 v2 = *(float2*)&acc[i][2];
        float2 v3 = *(float2*)&acc[i][3];
        size_t rb = ((size_t)ks * NB + m0 + mt + i) * NP + n0;
        *(float4*)&g_simp[rb + c0] = make_float4(v0.x, v0.y, v1.x, v1.y);
        *(float4*)&g_simp[rb + c1] = make_float4(v2.x, v2.y, v3.x, v3.y);
    }
}

// ---------------- K4: fused gumbel top-k selection + gather ---------------
__device__ __forceinline__ float gumbelf(float u) {
    float t = -logf(u + 1e-10f);
    return -logf(t + 1e-10f);
}

__global__ void k_select_gather(const float* __restrict__ gum,
                                const float* __restrict__ prompt,
                                float* __restrict__ out) {
    __shared__ float wval[16];
    __shared__ int   widx[16];
    __shared__ int   best[TOPK];
    int b = blockIdx.x, p = threadIdx.x;
    int lane = p & 31, w = p >> 5;

    // reduce split-K partials, apply deferred normalization
    float cur = 0.f;
#pragma unroll
    for (int s = 0; s < SPLITK; ++s)
        cur += g_simp[((size_t)s * NB + b) * NP + p];
    cur *= g_qs[b] * g_ks[p];

    float g[TOPK];
#pragma unroll
    for (int i = 0; i < TOPK; ++i)
        g[i] = gumbelf(gum[((size_t)i * NB + b) * NP + p]);

    // sim in [-1,1], gumbel in [-3.2, 23.1] => a selected entry at -1000 can
    // never win again, so mask-out == index exclusion.
    for (int i = 0; i < TOPK; ++i) {
        bool excl = false;
#pragma unroll
        for (int j = 0; j < TOPK; ++j)
            if (j < i && best[j] == p) excl = true;
        float v = excl ? -1e30f : cur + g[i];
        int idx = p;
#pragma unroll
        for (int o = 16; o > 0; o >>= 1) {
            float ov = __shfl_down_sync(0xFFFFFFFFu, v, o);
            int   oi = __shfl_down_sync(0xFFFFFFFFu, idx, o);
            if (ov > v || (ov == v && oi < idx)) { v = ov; idx = oi; }
        }
        if (lane == 0) { wval[w] = v; widx[w] = idx; }
        __syncthreads();
        if (w == 0) {
            float v2 = wval[lane & 15];
            int   i2 = widx[lane & 15];
#pragma unroll
            for (int o = 8; o > 0; o >>= 1) {
                float ov = __shfl_down_sync(0xFFFFFFFFu, v2, o);
                int   oi = __shfl_down_sync(0xFFFFFFFFu, i2, o);
                if (ov > v2 || (ov == v2 && oi < i2)) { v2 = ov; i2 = oi; }
            }
            if (lane == 0) best[i] = i2;
        }
        __syncthreads();
    }

    // gather: out[b, i*L + l, :] = prompt[best[i], l, :]  (512 threads)
    float4* ob = (float4*)out + (size_t)b * TOPK * NL * (ND / 4);
#pragma unroll
    for (int i = 0; i < TOPK; ++i) {
        const float4* src = (const float4*)prompt + (size_t)best[i] * NL * (ND / 4);
        float4* dst = ob + i * NL * (ND / 4);
#pragma unroll
        for (int j = 0; j < 4; ++j)
            dst[p + 512 * j] = src[p + 512 * j];
    }
}

// ---------------- launch ----------------
extern "C" void kernel_launch(void* const* d_in, const int* in_sizes, int n_in,
                              void* d_out, int out_size) {
    const float* x      = (const float*)d_in[0];  // [256,196,1024]
    const float* prompt = (const float*)d_in[1];  // [512,8,1024]
    const float* key    = (const float*)d_in[2];  // [512,1024]
    const float* gum    = (const float*)d_in[3];  // [4,256,512]
    float* out          = (float*)d_out;          // [256,32,1024]

    k_mean_partial<<<dim3(NB, SSPLIT), 256>>>(x);
    k_norms<<<NB + NP, 256>>>(key);
    k_gemm<<<dim3(NP / TN, NB / TM, SPLITK), 256>>>(key);
    k_select_gather<<<NB, NP>>>(gum, prompt, out);
}

// round 8
// speedup vs baseline: 1.4958x; 1.0360x over previous
#include <cuda_runtime.h>
#include <math.h>

#define NB 256      // batch
#define NS 196      // seq
#define ND 1024     // dim
#define NP 512      // pool
#define NL 8        // length
#define TOPK 4
#define SSPLIT 7
#define SCHUNK 28   // 196/7

// GEMM config
#define TM 64
#define TN 128
#define GKC 32
#define SPLITK 8
#define KSLICE (ND / SPLITK)   // 128
#define ARS 132                // As2 row stride (floats)
#define BRS 132                // Bs row stride (floats), plain layout

// K1 fused grid partition
#define K1_PART (NB * SSPLIT)          // 1792 partial-mean blocks
#define K1_KEY  (K1_PART + NP)         // +512 key-norm blocks
#define NGUM    (TOPK * NB * NP)       // 524288 gumbel values
#define K1_GUM  (K1_KEY + NGUM / 1024) // +512 gumbel blocks (256 thr x 4)

// ---------------- scratch (no allocations allowed) ----------------
__device__ float g_part[SSPLIT * NB * ND];       // partial sums (7 MB)
__device__ float g_q[NB * ND];                   // mean query (un-normalized)
__device__ float g_qs[NB];                       // 1/||q|| per batch
__device__ float g_ks[NP];                       // 1/||k|| per pool row
__device__ float g_simp[SPLITK * NB * NP];       // split-K raw-dot partials
__device__ float g_gum[NGUM];                    // precomputed gumbel noise

// packed dual-fp32 FMA (sm_100+): bitwise-identical to two scalar FFMAs
__device__ __forceinline__ unsigned long long ffma2(unsigned long long a,
                                                    unsigned long long b,
                                                    unsigned long long c) {
    unsigned long long d;
    asm("fma.rn.f32x2 %0, %1, %2, %3;" : "=l"(d) : "l"(a), "l"(b), "l"(c));
    return d;
}

__device__ __forceinline__ float gumbelf(float u) {
    float t = -logf(u + 1e-10f);
    return -logf(t + 1e-10f);
}

// ---------------- K1: partial means + key norms + gumbel precompute -------
__global__ void k1_fused(const float* __restrict__ x,
                         const float* __restrict__ key,
                         const float* __restrict__ gum) {
    int blk = blockIdx.x, tid = threadIdx.x;
    if (blk < K1_PART) {
        int sp = blk / NB, b = blk - sp * NB;
        const float4* xp = (const float4*)x + (size_t)(b * NS + sp * SCHUNK) * (ND / 4) + tid;
        float4 a0 = make_float4(0.f, 0.f, 0.f, 0.f);
        float4 a1 = make_float4(0.f, 0.f, 0.f, 0.f);
#pragma unroll 14
        for (int s = 0; s < SCHUNK; s += 2) {
            float4 v0 = __ldcs(&xp[(size_t)s * (ND / 4)]);
            float4 v1 = __ldcs(&xp[(size_t)(s + 1) * (ND / 4)]);
            a0.x += v0.x; a0.y += v0.y; a0.z += v0.z; a0.w += v0.w;
            a1.x += v1.x; a1.y += v1.y; a1.z += v1.z; a1.w += v1.w;
        }
        a0.x += a1.x; a0.y += a1.y; a0.z += a1.z; a0.w += a1.w;
        ((float4*)g_part)[(sp * NB + blk - sp * NB) * (ND / 4) + tid] = a0;
    } else if (blk < K1_KEY) {
        __shared__ float red[256];
        int kp = blk - K1_PART;
        float4 v = ((const float4*)key)[kp * (ND / 4) + tid];
        red[tid] = v.x * v.x + v.y * v.y + v.z * v.z + v.w * v.w;
        __syncthreads();
        for (int s = 128; s > 0; s >>= 1) {
            if (tid < s) red[tid] += red[tid + s];
            __syncthreads();
        }
        if (tid == 0) g_ks[kp] = rsqrtf(fmaxf(red[0], 1e-12f));
    } else {
        int base = (blk - K1_KEY) * 1024 + tid;
#pragma unroll
        for (int j = 0; j < 4; ++j) {
            int idx = base + j * 256;
            g_gum[idx] = gumbelf(gum[idx]);
        }
    }
}

// ---------------- K2: combine partials -> mean query + its inverse norm ---
__global__ void k_norms() {
    __shared__ float red[256];
    int blk = blockIdx.x, tid = threadIdx.x;
    const float4* pp = (const float4*)g_part;
    float4 acc = pp[(0 * NB + blk) * (ND / 4) + tid];
#pragma unroll
    for (int s = 1; s < SSPLIT; ++s) {
        float4 p = pp[(s * NB + blk) * (ND / 4) + tid];
        acc.x += p.x; acc.y += p.y; acc.z += p.z; acc.w += p.w;
    }
    float4 q;
    q.x = acc.x / (float)NS; q.y = acc.y / (float)NS;
    q.z = acc.z / (float)NS; q.w = acc.w / (float)NS;
    ((float4*)g_q)[blk * (ND / 4) + tid] = q;
    float ss = q.x * q.x + q.y * q.y + q.z * q.z + q.w * q.w;
    red[tid] = ss;
    __syncthreads();
    for (int s = 128; s > 0; s >>= 1) {
        if (tid < s) red[tid] += red[tid + s];
        __syncthreads();
    }
    if (tid == 0) g_qs[blk] = rsqrtf(fmaxf(red[0], 1e-12f));
}

// ---------------- K3: raw dots = g_q @ key^T (split-K, FFMA2) -------------
// 64x128 tile, 256 threads (8 warps as 4x2, lanes as 4x8), 4 rows x 8 cols
// per thread. Per-lane B columns {wn*64+lc*4..+3} and {+32..+35}: LDS.64
// reads hit 8 distinct bank pairs -> conflict-free, no skew.
__global__ void k_gemm(const float* __restrict__ key) {
    __shared__ __align__(16) float As2[GKC][ARS];   // [k][2*m] duplicated
    __shared__ __align__(16) float Bs[GKC][BRS];    // [k][n] plain
    int tid = threadIdx.x;
    int n0 = blockIdx.x * TN, m0 = blockIdx.y * TM, ks = blockIdx.z;
    int k0 = ks * KSLICE;

    int w = tid >> 5, lane = tid & 31;
    int wm = w & 3, wn = w >> 2;
    int lr = lane >> 3, lc = lane & 7;
    int aoff = 2 * (wm * 16 + lr * 4);
    int c0 = wn * 64 + lc * 4;
    int c1 = c0 + 32;

    int am = tid >> 3;          // 0..31
    int kq = tid & 7;           // float4 within 32-k chunk

    const float4* Ag = (const float4*)g_q;
    const float4* Bg = (const float4*)key;

    unsigned long long acc[4][4];
#pragma unroll
    for (int i = 0; i < 4; ++i)
#pragma unroll
        for (int j = 0; j < 4; ++j) acc[i][j] = 0ULL;

    int kb = (k0 >> 2) + kq;
    float4 pa0 = Ag[(m0 + am) * (ND / 4) + kb];
    float4 pa1 = Ag[(m0 + am + 32) * (ND / 4) + kb];
    float4 pb0 = Bg[(n0 + am) * (ND / 4) + kb];
    float4 pb1 = Bg[(n0 + am + 32) * (ND / 4) + kb];
    float4 pb2 = Bg[(n0 + am + 64) * (ND / 4) + kb];
    float4 pb3 = Bg[(n0 + am + 96) * (ND / 4) + kb];

    for (int kt = 0; kt < KSLICE; kt += GKC) {
        __syncthreads();
        int kk = kq * 4;
        *(float2*)&As2[kk + 0][2 * am] = make_float2(pa0.x, pa0.x);
        *(float2*)&As2[kk + 1][2 * am] = make_float2(pa0.y, pa0.y);
        *(float2*)&As2[kk + 2][2 * am] = make_float2(pa0.z, pa0.z);
        *(float2*)&As2[kk + 3][2 * am] = make_float2(pa0.w, pa0.w);
        *(float2*)&As2[kk + 0][2 * (am + 32)] = make_float2(pa1.x, pa1.x);
        *(float2*)&As2[kk + 1][2 * (am + 32)] = make_float2(pa1.y, pa1.y);
        *(float2*)&As2[kk + 2][2 * (am + 32)] = make_float2(pa1.z, pa1.z);
        *(float2*)&As2[kk + 3][2 * (am + 32)] = make_float2(pa1.w, pa1.w);
        Bs[kk + 0][am]      = pb0.x; Bs[kk + 1][am]      = pb0.y;
        Bs[kk + 2][am]      = pb0.z; Bs[kk + 3][am]      = pb0.w;
        Bs[kk + 0][am + 32] = pb1.x; Bs[kk + 1][am + 32] = pb1.y;
        Bs[kk + 2][am + 32] = pb1.z; Bs[kk + 3][am + 32] = pb1.w;
        Bs[kk + 0][am + 64] = pb2.x; Bs[kk + 1][am + 64] = pb2.y;
        Bs[kk + 2][am + 64] = pb2.z; Bs[kk + 3][am + 64] = pb2.w;
        Bs[kk + 0][am + 96] = pb3.x; Bs[kk + 1][am + 96] = pb3.y;
        Bs[kk + 2][am + 96] = pb3.z; Bs[kk + 3][am + 96] = pb3.w;
        __syncthreads();
        if (kt + GKC < KSLICE) {
            int kb2 = ((k0 + kt + GKC) >> 2) + kq;
            pa0 = Ag[(m0 + am) * (ND / 4) + kb2];
            pa1 = Ag[(m0 + am + 32) * (ND / 4) + kb2];
            pb0 = Bg[(n0 + am) * (ND / 4) + kb2];
            pb1 = Bg[(n0 + am + 32) * (ND / 4) + kb2];
            pb2 = Bg[(n0 + am + 64) * (ND / 4) + kb2];
            pb3 = Bg[(n0 + am + 96) * (ND / 4) + kb2];
        }
#pragma unroll
        for (int k = 0; k < GKC; ++k) {
            unsigned long long a0 = *(const unsigned long long*)&As2[k][aoff + 0];
            unsigned long long a1 = *(const unsigned long long*)&As2[k][aoff + 2];
            unsigned long long a2 = *(const unsigned long long*)&As2[k][aoff + 4];
            unsigned long long a3 = *(const unsigned long long*)&As2[k][aoff + 6];
            unsigned long long b0 = *(const unsigned long long*)&Bs[k][c0 + 0];
            unsigned long long b1 = *(const unsigned long long*)&Bs[k][c0 + 2];
            unsigned long long b2 = *(const unsigned long long*)&Bs[k][c1 + 0];
            unsigned long long b3 = *(const unsigned long long*)&Bs[k][c1 + 2];
            acc[0][0] = ffma2(a0, b0, acc[0][0]); acc[0][1] = ffma2(a0, b1, acc[0][1]);
            acc[0][2] = ffma2(a0, b2, acc[0][2]); acc[0][3] = ffma2(a0, b3, acc[0][3]);
            acc[1][0] = ffma2(a1, b0, acc[1][0]); acc[1][1] = ffma2(a1, b1, acc[1][1]);
            acc[1][2] = ffma2(a1, b2, acc[1][2]); acc[1][3] = ffma2(a1, b3, acc[1][3]);
            acc[2][0] = ffma2(a2, b0, acc[2][0]); acc[2][1] = ffma2(a2, b1, acc[2][1]);
            acc[2][2] = ffma2(a2, b2, acc[2][2]); acc[2][3] = ffma2(a2, b3, acc[2][3]);
            acc[3][0] = ffma2(a3, b0, acc[3][0]); acc[3][1] = ffma2(a3, b1, acc[3][1]);
            acc[3][2] = ffma2(a3, b2, acc[3][2]); acc[3][3] = ffma2(a3, b3, acc[3][3]);
        }
    }
    int mt = wm * 16 + lr * 4;
#pragma unroll
    for (int i = 0; i < 4; ++i) {
        float2 v0 = *(float2*)&acc[i][0];
        float2 v1 = *(float2*)&acc[i][1];
        float2 v2 = *(float2*)&acc[i][2];
        float2 v3 = *(float2*)&acc[i][3];
        size_t rb = ((size_t)ks * NB + m0 + mt + i) * NP + n0;
        *(float4*)&g_simp[rb + c0] = make_float4(v0.x, v0.y, v1.x, v1.y);
        *(float4*)&g_simp[rb + c1] = make_float4(v2.x, v2.y, v3.x, v3.y);
    }
}

// ---------------- K4: selection with software-pipelined gather ------------
__global__ void k_select_gather(const float* __restrict__ prompt,
                                float* __restrict__ out) {
    __shared__ float wval[16];
    __shared__ int   widx[16];
    __shared__ int   best[TOPK];
    int b = blockIdx.x, p = threadIdx.x;
    int lane = p & 31, w = p >> 5;

    // reduce split-K partials, apply deferred normalization
    float cur = 0.f;
#pragma unroll
    for (int s = 0; s < SPLITK; ++s)
        cur += g_simp[((size_t)s * NB + b) * NP + p];
    cur *= g_qs[b] * g_ks[p];

    float g[TOPK];
#pragma unroll
    for (int i = 0; i < TOPK; ++i)
        g[i] = g_gum[((size_t)i * NB + b) * NP + p];

    float4* ob = (float4*)out + (size_t)b * TOPK * NL * (ND / 4);
    float4 rv[4];

    // sim in [-1,1], gumbel in [-3.2, 23.1] => a selected entry at -1000 can
    // never win again, so mask-out == index exclusion.
    for (int i = 0; i < TOPK; ++i) {
        bool excl = false;
#pragma unroll
        for (int j = 0; j < TOPK; ++j)
            if (j < i && best[j] == p) excl = true;
        float v = excl ? -1e30f : cur + g[i];
        int idx = p;
#pragma unroll
        for (int o = 16; o > 0; o >>= 1) {
            float ov = __shfl_down_sync(0xFFFFFFFFu, v, o);
            int   oi = __shfl_down_sync(0xFFFFFFFFu, idx, o);
            if (ov > v || (ov == v && oi < idx)) { v = ov; idx = oi; }
        }
        if (lane == 0) { wval[w] = v; widx[w] = idx; }
        __syncthreads();
        if (w == 0) {
            float v2 = wval[lane & 15];
            int   i2 = widx[lane & 15];
#pragma unroll
            for (int o = 8; o > 0; o >>= 1) {
                float ov = __shfl_down_sync(0xFFFFFFFFu, v2, o);
                int   oi = __shfl_down_sync(0xFFFFFFFFu, i2, o);
                if (ov > v2 || (ov == v2 && oi < i2)) { v2 = ov; i2 = oi; }
            }
            if (lane == 0) best[i] = i2;
        }
        __syncthreads();

        // pipeline: drain previous selection's registers, launch this one's loads
        int sel = best[i];
        if (i > 0) {
            float4* dst = ob + (i - 1) * NL * (ND / 4);
#pragma unroll
            for (int j = 0; j < 4; ++j)
                dst[p + 512 * j] = rv[j];
        }
        const float4* src = (const float4*)prompt + (size_t)sel * NL * (ND / 4);
#pragma unroll
        for (int j = 0; j < 4; ++j)
            rv[j] = src[p + 512 * j];
    }
    {
        float4* dst = ob + (TOPK - 1) * NL * (ND / 4);
#pragma unroll
        for (int j = 0; j < 4; ++j)
            dst[p + 512 * j] = rv[j];
    }
}

// ---------------- launch ----------------
extern "C" void kernel_launch(void* const* d_in, const int* in_sizes, int n_in,
                              void* d_out, int out_size) {
    const float* x      = (const float*)d_in[0];  // [256,196,1024]
    const float* prompt = (const float*)d_in[1];  // [512,8,1024]
    const float* key    = (const float*)d_in[2];  // [512,1024]
    const float* gum    = (const float*)d_in[3];  // [4,256,512]
    float* out          = (float*)d_out;          // [256,32,1024]

    k1_fused<<<K1_GUM, 256>>>(x, key, gum);
    k_norms<<<NB, 256>>>();
    k_gemm<<<dim3(NP / TN, NB / TM, SPLITK), 256>>>(key);
    k_select_gather<<<NB, NP>>>(prompt, out);
}